// round 1
// baseline (speedup 1.0000x reference)
#include <cuda_runtime.h>

// Vector_Quantizer eval forward:
//   x: [32,64,64,64] f32, embedding: [1024,64] f32
//   out (float32, 8519681): [loss(1) | quantized(8388608, BCHW) | indices(131072)]
//
// Strategy: distance argmin is an fp32 "GEMM" (131072x1024x64 MAC) -> fp32 FMA bound.
// Use packed fma.rn.f32x2 (2x FFMA throughput on sm_103a), packing lanes along C.
// 128-pixel blocks, 128-code smem tiles, 8x8 register tile per thread.

#define KCODES 1024
#define CDIM 64
#define NPIX 131072
#define PIX_PER_BLK 128
#define CODE_TILE 128
#define NTILES (KCODES / CODE_TILE)
#define PAD 68          // floats per smem row: 16B-aligned, avoids 0 mod 32 bank stride
#define QELEMS 8388608  // 32*64*64*64

__device__ float g_enorm[KCODES];
__device__ float g_loss;

__global__ void vq_prep(const float* __restrict__ emb) {
    int k = blockIdx.x * blockDim.x + threadIdx.x;
    if (k == 0) g_loss = 0.0f;
    if (k < KCODES) {
        const float4* r = reinterpret_cast<const float4*>(emb + k * CDIM);
        float s = 0.0f;
#pragma unroll
        for (int i = 0; i < CDIM / 4; i++) {
            float4 v = r[i];
            s += v.x * v.x + v.y * v.y + v.z * v.z + v.w * v.w;
        }
        g_enorm[k] = s;
    }
}

struct SmemLayout {
    float sxT[PIX_PER_BLK][PAD];   // x transposed: [pixel][c]
    float se[CODE_TILE][PAD];      // e tile row-major: [code][c]
    float red_s[16][PIX_PER_BLK];
    int   red_i[16][PIX_PER_BLK];
    int   bidx[PIX_PER_BLK];
    float wsum[8];
};

__device__ __forceinline__ void ffma2(unsigned long long& d,
                                      unsigned long long a,
                                      unsigned long long b) {
    asm("fma.rn.f32x2 %0, %1, %2, %0;" : "+l"(d) : "l"(a), "l"(b));
}

extern __shared__ char smem_raw[];

__global__ void __launch_bounds__(256) vq_main(const float* __restrict__ x,
                                               const float* __restrict__ emb,
                                               float* __restrict__ out) {
    SmemLayout& s = *reinterpret_cast<SmemLayout*>(smem_raw);
    const int tid = threadIdx.x;
    const int pg = tid & 15;   // pixel group: pixels pg, pg+16, ..., pg+112
    const int cg = tid >> 4;   // code group: codes cg*8 .. cg*8+7 per tile
    const int n0 = blockIdx.x * PIX_PER_BLK;
    const int b = n0 >> 12;          // batch index (4096 pixels per batch image)
    const int rem = n0 & 4095;       // h*64+w offset within image
    const float* xbase = x + (size_t)b * 262144 + rem;

    // --- Load x tile transposed into smem (scalar: coalesced global, 4-way STS) ---
    for (int i = tid; i < CDIM * PIX_PER_BLK; i += 256) {
        int c = i >> 7, px = i & 127;
        s.sxT[px][c] = xbase[c * 4096 + px];
    }

    float best_s[8];
    int best_i[8];
#pragma unroll
    for (int i = 0; i < 8; i++) { best_s[i] = 3.4e38f; best_i[i] = 0; }

    for (int t = 0; t < NTILES; t++) {
        __syncthreads();  // previous tile's reads done before overwrite
        // --- Load 128-code tile (contiguous 32KB from global/L2, row-major copy) ---
        const float4* esrc = reinterpret_cast<const float4*>(emb + t * CODE_TILE * CDIM);
        for (int i = tid; i < CODE_TILE * (CDIM / 4); i += 256) {
            int k = i >> 4, c4 = i & 15;
            *reinterpret_cast<float4*>(&s.se[k][c4 * 4]) = esrc[i];
        }
        __syncthreads();

        // --- 8 pixels x 8 codes register tile, f32x2 packed along C ---
        unsigned long long acc[8][8];
#pragma unroll
        for (int i = 0; i < 8; i++)
#pragma unroll
            for (int j = 0; j < 8; j++) acc[i][j] = 0ULL;

#pragma unroll 8
        for (int c = 0; c < CDIM; c += 4) {
            ulonglong2 xv[8], ev[8];
#pragma unroll
            for (int i = 0; i < 8; i++)
                xv[i] = *reinterpret_cast<const ulonglong2*>(&s.sxT[pg + 16 * i][c]);
#pragma unroll
            for (int j = 0; j < 8; j++)
                ev[j] = *reinterpret_cast<const ulonglong2*>(&s.se[cg * 8 + j][c]);
#pragma unroll
            for (int i = 0; i < 8; i++)
#pragma unroll
                for (int j = 0; j < 8; j++) {
                    ffma2(acc[i][j], xv[i].x, ev[j].x);
                    ffma2(acc[i][j], xv[i].y, ev[j].y);
                }
        }

        // --- Fold into running argmin: score = ||e||^2 - 2*dot (||x||^2 is constant) ---
#pragma unroll
        for (int j = 0; j < 8; j++) {
            int k = t * CODE_TILE + cg * 8 + j;
            float en = g_enorm[k];
#pragma unroll
            for (int i = 0; i < 8; i++) {
                float lo, hi;
                asm("mov.b64 {%0, %1}, %2;" : "=f"(lo), "=f"(hi) : "l"(acc[i][j]));
                float sc = fmaf(-2.0f, lo + hi, en);
                if (sc < best_s[i]) { best_s[i] = sc; best_i[i] = k; }
            }
        }
    }

    // --- Cross-thread reduction over the 16 code groups ---
    __syncthreads();
#pragma unroll
    for (int i = 0; i < 8; i++) {
        s.red_s[cg][pg + 16 * i] = best_s[i];
        s.red_i[cg][pg + 16 * i] = best_i[i];
    }
    __syncthreads();
    if (tid < PIX_PER_BLK) {
        int px = tid;
        float bs = s.red_s[0][px];
        int bi = s.red_i[0][px];
#pragma unroll
        for (int g = 1; g < 16; g++) {
            float v = s.red_s[g][px];
            int id = s.red_i[g][px];
            if (v < bs || (v == bs && id < bi)) { bs = v; bi = id; }
        }
        s.bidx[px] = bi;
        out[1 + QELEMS + n0 + px] = (float)bi;  // indices as float
    }
    __syncthreads();

    // --- Epilogue: gather quantized, write BCHW, accumulate exact loss ---
    {
        int px = tid & 127;
        int ch = tid >> 7;  // two threads per pixel, each handles 32 of 64 channels
        int bi = s.bidx[px];
        const float4* erow = reinterpret_cast<const float4*>(emb + bi * CDIM);
        float* qout = out + 1 + (size_t)b * 262144 + rem + px;
        float lsum = 0.0f;
#pragma unroll
        for (int cc = 0; cc < 8; cc++) {
            int c = ch * 32 + cc * 4;
            float4 e4 = erow[c >> 2];
            float4 x4 = *reinterpret_cast<const float4*>(&s.sxT[px][c]);
            float d0 = e4.x - x4.x, d1 = e4.y - x4.y;
            float d2 = e4.z - x4.z, d3 = e4.w - x4.w;
            lsum += d0 * d0 + d1 * d1 + d2 * d2 + d3 * d3;
            qout[(size_t)(c + 0) * 4096] = e4.x;
            qout[(size_t)(c + 1) * 4096] = e4.y;
            qout[(size_t)(c + 2) * 4096] = e4.z;
            qout[(size_t)(c + 3) * 4096] = e4.w;
        }
#pragma unroll
        for (int o = 16; o > 0; o >>= 1)
            lsum += __shfl_down_sync(0xffffffffu, lsum, o);
        if ((tid & 31) == 0) s.wsum[tid >> 5] = lsum;
        __syncthreads();
        if (tid == 0) {
            float bsum = 0.0f;
#pragma unroll
            for (int w = 0; w < 8; w++) bsum += s.wsum[w];
            atomicAdd(&g_loss, bsum);
        }
    }
}

__global__ void vq_fin(float* __restrict__ out) {
    out[0] = 0.25f * g_loss * (1.0f / (float)QELEMS);
}

extern "C" void kernel_launch(void* const* d_in, const int* in_sizes, int n_in,
                              void* d_out, int out_size) {
    const float* x = (const float*)d_in[0];
    const float* emb = (const float*)d_in[1];
    // Defensive: swap if metadata order is (embedding, x)
    if (n_in >= 2 && in_sizes[0] == KCODES * CDIM && in_sizes[1] == NPIX * CDIM) {
        const float* tmp = x; x = emb; emb = tmp;
    }
    float* out = (float*)d_out;
    (void)out_size;

    cudaFuncSetAttribute(vq_main, cudaFuncAttributeMaxDynamicSharedMemorySize,
                         (int)sizeof(SmemLayout));

    vq_prep<<<(KCODES + 255) / 256, 256>>>(emb);
    vq_main<<<NPIX / PIX_PER_BLK, 256, sizeof(SmemLayout)>>>(x, emb, out);
    vq_fin<<<1, 1>>>(out);
}